// round 17
// baseline (speedup 1.0000x reference)
#include <cuda_runtime.h>
#include <cuda_bf16.h>
#include <cstdint>

#define DI __device__ __forceinline__

static constexpr int   NN     = 8192;
static constexpr int   DD     = 256;
static constexpr float EPS    = 1e-8f;
static constexpr float THR    = 1e-6f;
static constexpr float LN_EPS = 1e-5f;

// ---------------- device scratch ----------------
__device__ float          g_part[4 * NN];
__device__ float          g_wsum[NN];
__device__ float          g_T[(size_t)NN * DD];
__device__ __nv_bfloat16  g_Tbf[(size_t)NN * DD];
__device__ float          g_numA[(size_t)NN * DD];
__device__ float          g_numB[(size_t)NN * DD];
__device__ float          g_numC[(size_t)NN * DD];

// ---------------- helpers ----------------
DI uint32_t smem_u32(const void* p) {
    uint32_t a;
    asm("{ .reg .u64 t; cvta.to.shared.u64 t, %1; cvt.u32.u64 %0, t; }" : "=r"(a) : "l"(p));
    return a;
}
DI void ldsm4t(uint32_t* r, uint32_t addr) {
    asm volatile("ldmatrix.sync.aligned.m8n8.x4.trans.shared.b16 {%0,%1,%2,%3}, [%4];"
        : "=r"(r[0]), "=r"(r[1]), "=r"(r[2]), "=r"(r[3]) : "r"(addr));
}
DI void ldsm4(uint32_t* r, uint32_t addr) {
    asm volatile("ldmatrix.sync.aligned.m8n8.x4.shared.b16 {%0,%1,%2,%3}, [%4];"
        : "=r"(r[0]), "=r"(r[1]), "=r"(r[2]), "=r"(r[3]) : "r"(addr));
}
DI void mma_bf16(float* c, const uint32_t* a, const uint32_t* b) {
    asm volatile(
        "mma.sync.aligned.m16n8k16.row.col.f32.bf16.bf16.f32 "
        "{%0,%1,%2,%3}, {%4,%5,%6,%7}, {%8,%9}, {%0,%1,%2,%3};"
        : "+f"(c[0]), "+f"(c[1]), "+f"(c[2]), "+f"(c[3])
        : "r"(a[0]), "r"(a[1]), "r"(a[2]), "r"(a[3]), "r"(b[0]), "r"(b[1]));
}
DI uint32_t bf2u(float lo, float hi) {
    uint32_t r;
    asm("cvt.rn.bf16x2.f32 %0, %1, %2;" : "=r"(r) : "f"(hi), "f"(lo));
    return r;
}
DI uint4 cvt8bf(float4 a, float4 b) {
    uint4 u;
    u.x = bf2u(a.x, a.y); u.y = bf2u(a.z, a.w);
    u.z = bf2u(b.x, b.y); u.w = bf2u(b.z, b.w);
    return u;
}

// ================= kernel 1: FUSED T GEMM (bid<128) + colsum (bid>=128) =========
// Long t-branch CTAs scheduled FIRST (LPT) so they overlap the colsum stream.
static constexpr int AP = 40;
static constexpr int BP = 136;
static constexpr uint32_t PRE_SMEM = 2u * 128u * AP * 2u + 2u * 32u * BP * 2u;

__global__ void __launch_bounds__(256) pre_kernel(const float* __restrict__ M,
                                                  const float* __restrict__ X,
                                                  const float* __restrict__ W_in,
                                                  const float* __restrict__ b_in) {
    extern __shared__ char ps[];
    int tid = threadIdx.x;

    if (blockIdx.x >= 128) {
        // ---------------- colsum branch ----------------
        float* red = (float*)ps;
        int cbid = blockIdx.x - 128;
        int it = cbid >> 2, quart = cbid & 3;
        int i0 = it * 128;
        int rg = tid >> 5, i4 = (tid & 31) * 4;

        if (quart == 0 && tid < 128) g_wsum[i0 + tid] = 0.f;

        float a0 = 0.f, a1 = 0.f, a2 = 0.f, a3 = 0.f;
        int rbeg = quart * 2048 + rg, rend = quart * 2048 + 2048;
        for (int r = rbeg; r < rend; r += 32) {
            float4 m0 = *(const float4*)&M[(size_t)(r     ) * NN + i0 + i4];
            float4 m1 = *(const float4*)&M[(size_t)(r +  8) * NN + i0 + i4];
            float4 m2 = *(const float4*)&M[(size_t)(r + 16) * NN + i0 + i4];
            float4 m3 = *(const float4*)&M[(size_t)(r + 24) * NN + i0 + i4];
            a0 += m0.x + m1.x + m2.x + m3.x;
            a1 += m0.y + m1.y + m2.y + m3.y;
            a2 += m0.z + m1.z + m2.z + m3.z;
            a3 += m0.w + m1.w + m2.w + m3.w;
        }
        red[rg * 128 + i4 + 0] = a0; red[rg * 128 + i4 + 1] = a1;
        red[rg * 128 + i4 + 2] = a2; red[rg * 128 + i4 + 3] = a3;
        __syncthreads();
        if (tid < 128) {
            float s = 0.f;
#pragma unroll
            for (int g = 0; g < 8; g++) s += red[g * 128 + tid];
            g_part[quart * NN + i0 + tid] = s;
        }
        return;
    }

    // ---------------- T = X @ W_in + b_in branch (W_in converted inline) -------
    int bid = blockIdx.x;                              // 0..127
    __nv_bfloat16* sA0 = (__nv_bfloat16*)ps;
    __nv_bfloat16* sA1 = sA0 + 128 * AP;
    __nv_bfloat16* sB0 = sA1 + 128 * AP;
    __nv_bfloat16* sB1 = sB0 + 32 * BP;
    __nv_bfloat16* sAb[2] = { sA0, sA1 };
    __nv_bfloat16* sBb[2] = { sB0, sB1 };

    int j0 = (bid >> 1) * 128;
    int d0 = (bid & 1) * 128;

    int xj = tid >> 1, xh = (tid & 1) * 16;
    int wk = tid >> 3, wd = (tid & 7) * 16;

    int w = tid >> 5, lane = tid & 31;
    int iw = (w & 3) * 32, dw = (w >> 2) * 64;
    int q = lane >> 3, r7 = lane & 7;
    int l15 = lane & 15, lh = (lane >> 4) * 8;

    float acc[2][8][4] = {};
    float4 xr[4];
    uint4  wr[2];

    auto loadW = [&](int k0) {
        const float* wp = &W_in[(size_t)(k0 + wk) * DD + d0 + wd];
        float4 f0 = *(const float4*)(wp);
        float4 f1 = *(const float4*)(wp + 4);
        float4 f2 = *(const float4*)(wp + 8);
        float4 f3 = *(const float4*)(wp + 12);
        wr[0] = cvt8bf(f0, f1);
        wr[1] = cvt8bf(f2, f3);
    };

#pragma unroll
    for (int p = 0; p < 4; p++)
        xr[p] = *(const float4*)&X[(size_t)(j0 + xj) * DD + xh + p * 4];
    loadW(0);

    *(uint4*)&sAb[0][xj * AP + xh]     = cvt8bf(xr[0], xr[1]);
    *(uint4*)&sAb[0][xj * AP + xh + 8] = cvt8bf(xr[2], xr[3]);
    *(uint4*)&sBb[0][wk * BP + wd]     = wr[0];
    *(uint4*)&sBb[0][wk * BP + wd + 8] = wr[1];
    __syncthreads();

    const int NCk = DD / 32;
    int buf = 0;
    for (int c = 0; c < NCk; c++) {
        int nbuf = buf ^ 1;
        if (c + 1 < NCk) {
            int k0 = (c + 1) * 32;
#pragma unroll
            for (int p = 0; p < 4; p++)
                xr[p] = *(const float4*)&X[(size_t)(j0 + xj) * DD + k0 + xh + p * 4];
            loadW(k0);
        }
        uint32_t swb = smem_u32(sAb[buf]), stb = smem_u32(sBb[buf]);
#pragma unroll
        for (int kk = 0; kk < 32; kk += 16) {
            uint32_t a[2][4];
#pragma unroll
            for (int mb = 0; mb < 2; mb++)
                ldsm4(a[mb], swb + (uint32_t)(((iw + mb * 16 + l15) * AP + kk + lh) * 2));
#pragma unroll
            for (int nbp = 0; nbp < 4; nbp++) {
                uint32_t b[4];
                ldsm4t(b, stb + (uint32_t)(((kk + (q & 1) * 8 + r7) * BP + dw + (nbp * 2 + (q >> 1)) * 8) * 2));
                mma_bf16(acc[0][2 * nbp],     a[0], b);
                mma_bf16(acc[1][2 * nbp],     a[1], b);
                mma_bf16(acc[0][2 * nbp + 1], a[0], b + 2);
                mma_bf16(acc[1][2 * nbp + 1], a[1], b + 2);
            }
        }
        if (c + 1 < NCk) {
            *(uint4*)&sAb[nbuf][xj * AP + xh]     = cvt8bf(xr[0], xr[1]);
            *(uint4*)&sAb[nbuf][xj * AP + xh + 8] = cvt8bf(xr[2], xr[3]);
            *(uint4*)&sBb[nbuf][wk * BP + wd]     = wr[0];
            *(uint4*)&sBb[nbuf][wk * BP + wd + 8] = wr[1];
        }
        __syncthreads();
        buf = nbuf;
    }

    int gi = lane >> 2, gk = (lane & 3) * 2;
#pragma unroll
    for (int mb = 0; mb < 2; mb++)
#pragma unroll
        for (int nb = 0; nb < 8; nb++) {
            int dg = d0 + dw + nb * 8 + gk;
            float2 b2 = *(const float2*)&b_in[dg];
            float v0 = acc[mb][nb][0] + b2.x, v1 = acc[mb][nb][1] + b2.y;
            float v2 = acc[mb][nb][2] + b2.x, v3 = acc[mb][nb][3] + b2.y;
            size_t r0 = (size_t)(j0 + iw + mb * 16 + gi) * DD + dg;
            *(float2*)&g_T[r0]          = make_float2(v0, v1);
            *(float2*)&g_T[r0 + 8 * DD] = make_float2(v2, v3);
            *(uint32_t*)&g_Tbf[r0]          = bf2u(v0, v1);
            *(uint32_t*)&g_Tbf[r0 + 8 * DD] = bf2u(v2, v3);
        }
}

// ================= kernel 4: big GEMM (296 CTAs, 2/SM; inv computed locally) ====
static constexpr int PITCH = 136;

__global__ void __launch_bounds__(256, 2) mma_kernel(const float* __restrict__ M) {
    __shared__ __nv_bfloat16 sW[2][32 * PITCH];
    __shared__ __nv_bfloat16 sT[2][32 * PITCH];

    int tid = threadIdx.x;
    int bid = blockIdx.x;
    int tile, part, nparts, cbeg, NC;
    if (bid < 120) {
        tile = bid / 3; part = bid % 3; nparts = 3;
        cbeg = (part == 0) ? 0 : (86 + 85 * (part - 1));
        NC   = (part == 0) ? 86 : 85;
    } else {
        int b2 = bid - 120;
        tile = 40 + (b2 >> 1); part = b2 & 1; nparts = 2;
        cbeg = part * 128; NC = 128;
    }
    int it = tile >> 1, dt = tile & 1;
    int i0 = it * 128, d0 = dt * 128;

    int cj = tid >> 5;
    int ci = (tid & 31) * 4;
    float4 inv4;
    {
        float s[4];
#pragma unroll
        for (int p = 0; p < 4; p++) {
            int i = i0 + ci + p;
            s[p] = g_part[i] + g_part[NN + i] + g_part[2 * NN + i] + g_part[3 * NN + i];
        }
        inv4 = make_float4(1.f / (s[0] + EPS), 1.f / (s[1] + EPS),
                           1.f / (s[2] + EPS), 1.f / (s[3] + EPS));
    }
    float wa0 = 0.f, wa1 = 0.f, wa2 = 0.f, wa3 = 0.f;

    int tj = tid >> 4;
    int tc = (tid & 15) * 8;

    int w = tid >> 5, lane = tid & 31;
    int iw = (w & 3) * 32, dw = (w >> 2) * 64;
    int q  = lane >> 3, r7 = lane & 7;

    float acc[2][8][4] = {};

    const float*          Mb = M     + (size_t)cbeg * 32 * NN;
    const __nv_bfloat16*  Tb = g_Tbf + (size_t)cbeg * 32 * DD;

    float4 mr[4], tr[2];
#pragma unroll
    for (int jj = 0; jj < 4; jj++)
        mr[jj] = *(const float4*)&Mb[(size_t)(cj + jj * 8) * NN + i0 + ci];
#pragma unroll
    for (int jj = 0; jj < 2; jj++)
        tr[jj] = *(const float4*)&Tb[(size_t)(tj + jj * 16) * DD + d0 + tc];

#pragma unroll
    for (int jj = 0; jj < 4; jj++) {
        int j = cj + jj * 8;
        float w0 = mr[jj].x * inv4.x; w0 = (w0 > THR) ? w0 : 0.f;
        float w1 = mr[jj].y * inv4.y; w1 = (w1 > THR) ? w1 : 0.f;
        float w2 = mr[jj].z * inv4.z; w2 = (w2 > THR) ? w2 : 0.f;
        float w3 = mr[jj].w * inv4.w; w3 = (w3 > THR) ? w3 : 0.f;
        if (dt == 0) { wa0 += w0; wa1 += w1; wa2 += w2; wa3 += w3; }
        *(uint32_t*)&sW[0][j * PITCH + ci]     = bf2u(w0, w1);
        *(uint32_t*)&sW[0][j * PITCH + ci + 2] = bf2u(w2, w3);
    }
#pragma unroll
    for (int jj = 0; jj < 2; jj++)
        *(float4*)&sT[0][(tj + jj * 16) * PITCH + tc] = tr[jj];
    __syncthreads();

    int buf = 0;
    for (int c = 0; c < NC; c++) {
        int nbuf = buf ^ 1;
        if (c + 1 < NC) {
            size_t koff = (size_t)(c + 1) * 32;
#pragma unroll
            for (int jj = 0; jj < 4; jj++)
                mr[jj] = *(const float4*)&Mb[(koff + cj + jj * 8) * NN + i0 + ci];
#pragma unroll
            for (int jj = 0; jj < 2; jj++)
                tr[jj] = *(const float4*)&Tb[(koff + tj + jj * 16) * DD + d0 + tc];
        }

        uint32_t swb = smem_u32(sW[buf]), stb = smem_u32(sT[buf]);
#pragma unroll
        for (int kk = 0; kk < 32; kk += 16) {
            uint32_t a[2][4];
#pragma unroll
            for (int mb = 0; mb < 2; mb++)
                ldsm4t(a[mb], swb + (uint32_t)(((kk + (q >> 1) * 8 + r7) * PITCH + iw + mb * 16 + (q & 1) * 8) * 2));
#pragma unroll
            for (int nbp = 0; nbp < 4; nbp++) {
                uint32_t b[4];
                ldsm4t(b, stb + (uint32_t)(((kk + (q & 1) * 8 + r7) * PITCH + dw + (nbp * 2 + (q >> 1)) * 8) * 2));
                mma_bf16(acc[0][2 * nbp],     a[0], b);
                mma_bf16(acc[1][2 * nbp],     a[1], b);
                mma_bf16(acc[0][2 * nbp + 1], a[0], b + 2);
                mma_bf16(acc[1][2 * nbp + 1], a[1], b + 2);
            }
        }

        if (c + 1 < NC) {
#pragma unroll
            for (int jj = 0; jj < 4; jj++) {
                int j = cj + jj * 8;
                float w0 = mr[jj].x * inv4.x; w0 = (w0 > THR) ? w0 : 0.f;
                float w1 = mr[jj].y * inv4.y; w1 = (w1 > THR) ? w1 : 0.f;
                float w2 = mr[jj].z * inv4.z; w2 = (w2 > THR) ? w2 : 0.f;
                float w3 = mr[jj].w * inv4.w; w3 = (w3 > THR) ? w3 : 0.f;
                if (dt == 0) { wa0 += w0; wa1 += w1; wa2 += w2; wa3 += w3; }
                *(uint32_t*)&sW[nbuf][j * PITCH + ci]     = bf2u(w0, w1);
                *(uint32_t*)&sW[nbuf][j * PITCH + ci + 2] = bf2u(w2, w3);
            }
#pragma unroll
            for (int jj = 0; jj < 2; jj++)
                *(float4*)&sT[nbuf][(tj + jj * 16) * PITCH + tc] = tr[jj];
        }
        __syncthreads();
        buf = nbuf;
    }

    if (dt == 0) {
        atomicAdd(&g_wsum[i0 + ci + 0], wa0);
        atomicAdd(&g_wsum[i0 + ci + 1], wa1);
        atomicAdd(&g_wsum[i0 + ci + 2], wa2);
        atomicAdd(&g_wsum[i0 + ci + 3], wa3);
    }

    float* numOut = (part == 0) ? g_numA : (part == 1) ? g_numB : g_numC;
    int gi = lane >> 2, gk = (lane & 3) * 2;
#pragma unroll
    for (int mb = 0; mb < 2; mb++)
#pragma unroll
        for (int nb = 0; nb < 8; nb++) {
            int i = i0 + iw + mb * 16 + gi;
            int d = d0 + dw + nb * 8 + gk;
            float* p = &numOut[(size_t)i * DD + d];
            p[0]          = acc[mb][nb][0];
            p[1]          = acc[mb][nb][1];
            p[8 * DD]     = acc[mb][nb][2];
            p[8 * DD + 1] = acc[mb][nb][3];
        }
}

// ================= kernel 5: epilogue (256 CTAs x 32 rows, occ 2, dist-2 num) ====
static constexpr int EBP = 264;

__global__ void __launch_bounds__(256, 2) epi_kernel(const float* __restrict__ X,
                                                     const float* __restrict__ W_out,
                                                     const float* __restrict__ b_out,
                                                     const float* __restrict__ ln_s,
                                                     const float* __restrict__ ln_b,
                                                     float* __restrict__ out) {
    __shared__ __nv_bfloat16 sA[2][32 * AP];
    __shared__ __nv_bfloat16 sB[2][32 * EBP];
    __shared__ float2 red[32][4];
    __shared__ float  winv_s[32];
    __shared__ int    flag_s[32];

    int tid = threadIdx.x;
    int i0  = blockIdx.x * 32;
    bool three = (i0 < 2560);

    if (tid < 32) {
        float ws = g_wsum[i0 + tid];
        winv_s[tid] = 1.f / (ws + EPS);
        flag_s[tid] = (ws > 0.f) ? 1 : 0;
    }
    __syncthreads();

    int ar = tid >> 3, ac = (tid & 7) * 4;
    float wv = winv_s[ar];
    int   fl = flag_s[ar];
    int wk = tid >> 3, wd = (tid & 7) * 32;

    int w = tid >> 5, lane = tid & 31;
    int iwp = (w & 1) * 16, dwp = (w >> 1) * 64;
    int q  = lane >> 3, r7 = lane & 7;
    int l15 = lane & 15, lh = (lane >> 4) * 8;

    float acc[8][4] = {};
    float4 avA, avB;
    uint4  wr[4];

    auto loadA = [&](int k0, float4& av) {
        size_t base = (size_t)(i0 + ar) * DD + k0 + ac;
        if (fl) {
            float4 a4 = *(const float4*)&g_numA[base];
            float4 b4 = *(const float4*)&g_numB[base];
            float s0 = a4.x + b4.x, s1 = a4.y + b4.y, s2 = a4.z + b4.z, s3 = a4.w + b4.w;
            if (three) {
                float4 c4 = *(const float4*)&g_numC[base];
                s0 += c4.x; s1 += c4.y; s2 += c4.z; s3 += c4.w;
            }
            av = make_float4(s0 * wv, s1 * wv, s2 * wv, s3 * wv);
        } else {
            av = *(const float4*)&g_T[base];
        }
    };
    auto loadW = [&](int k0) {
#pragma unroll
        for (int p = 0; p < 4; p++) {
            const float* wp = &W_out[(size_t)(k0 + wk) * DD + wd + p * 8];
            float4 f0 = *(const float4*)(wp);
            float4 f1 = *(const float4*)(wp + 4);
            wr[p] = cvt8bf(f0, f1);
        }
    };

    // prologue: chunk 0 staged; chunk 1 num loaded into avA
    loadA(0, avA);
    loadW(0);
    {
        uint2 u; u.x = bf2u(avA.x, avA.y); u.y = bf2u(avA.z, avA.w);
        *(uint2*)&sA[0][ar * AP + ac] = u;
#pragma unroll
        for (int p = 0; p < 4; p++) *(uint4*)&sB[0][wk * EBP + wd + p * 8] = wr[p];
    }
    loadA(32, avA);
    __syncthreads();

    const int NCk = DD / 32;
    for (int c = 0; c < NCk; c++) {
        if (c + 2 < NCk) loadA((c + 2) * 32, avB);
        if (c + 1 < NCk) loadW((c + 1) * 32);

        uint32_t swb = smem_u32(sA[c & 1]), stb = smem_u32(sB[c & 1]);
#pragma unroll
        for (int kk = 0; kk < 32; kk += 16) {
            uint32_t a[4];
            ldsm4(a, swb + (uint32_t)(((iwp + l15) * AP + kk + lh) * 2));
#pragma unroll
            for (int nbp = 0; nbp < 4; nbp++) {
                uint32_t b[4];
                ldsm4t(b, stb + (uint32_t)(((kk + (q & 1) * 8 + r7) * EBP + dwp + (nbp * 2 + (q >> 1)) * 8) * 2));
                mma_bf16(acc[2 * nbp],     a, b);
                mma_bf16(acc[2 * nbp + 1], a, b + 2);
            }
        }
        if (c + 1 < NCk) {
            uint2 u; u.x = bf2u(avA.x, avA.y); u.y = bf2u(avA.z, avA.w);
            *(uint2*)&sA[(c + 1) & 1][ar * AP + ac] = u;
#pragma unroll
            for (int p = 0; p < 4; p++) *(uint4*)&sB[(c + 1) & 1][wk * EBP + wd + p * 8] = wr[p];
        }
        __syncthreads();
        avA = avB;
    }

    // ---- + b_out + X, then LayerNorm ----
    int gi = lane >> 2, gk = (lane & 3) * 2;
    int r0 = iwp + gi, r1 = r0 + 8;
    float s0 = 0.f, q0 = 0.f, s1 = 0.f, q1 = 0.f;
#pragma unroll
    for (int nb = 0; nb < 8; nb++) {
        int d = dwp + nb * 8 + gk;
        float2 b2 = *(const float2*)&b_out[d];
        float2 x0 = *(const float2*)&X[(size_t)(i0 + r0) * DD + d];
        float2 x1 = *(const float2*)&X[(size_t)(i0 + r1) * DD + d];
        acc[nb][0] += b2.x + x0.x; acc[nb][1] += b2.y + x0.y;
        acc[nb][2] += b2.x + x1.x; acc[nb][3] += b2.y + x1.y;
        s0 += acc[nb][0] + acc[nb][1]; q0 += acc[nb][0] * acc[nb][0] + acc[nb][1] * acc[nb][1];
        s1 += acc[nb][2] + acc[nb][3]; q1 += acc[nb][2] * acc[nb][2] + acc[nb][3] * acc[nb][3];
    }
#pragma unroll
    for (int o = 1; o <= 2; o <<= 1) {
        s0 += __shfl_xor_sync(0xFFFFFFFFu, s0, o);
        q0 += __shfl_xor_sync(0xFFFFFFFFu, q0, o);
        s1 += __shfl_xor_sync(0xFFFFFFFFu, s1, o);
        q1 += __shfl_xor_sync(0xFFFFFFFFu, q1, o);
    }
    int dwi = w >> 1;
    if (gk == 0) {
        red[r0][dwi] = make_float2(s0, q0);
        red[r1][dwi] = make_float2(s1, q1);
    }
    __syncthreads();
    float sm0 = 0.f, sq0 = 0.f, sm1 = 0.f, sq1 = 0.f;
#pragma unroll
    for (int p = 0; p < 4; p++) {
        float2 e0 = red[r0][p], e1 = red[r1][p];
        sm0 += e0.x; sq0 += e0.y;
        sm1 += e1.x; sq1 += e1.y;
    }
    float mu0 = sm0 * (1.f / 256.f);
    float mu1 = sm1 * (1.f / 256.f);
    float v0  = sq0 * (1.f / 256.f) - mu0 * mu0;
    float v1  = sq1 * (1.f / 256.f) - mu1 * mu1;
    float rs0 = rsqrtf(v0 + LN_EPS), rs1 = rsqrtf(v1 + LN_EPS);
#pragma unroll
    for (int nb = 0; nb < 8; nb++) {
        int d = dwp + nb * 8 + gk;
        float2 ls = *(const float2*)&ln_s[d];
        float2 lb = *(const float2*)&ln_b[d];
        *(float2*)&out[(size_t)(i0 + r0) * DD + d] =
            make_float2((acc[nb][0] - mu0) * rs0 * ls.x + lb.x,
                        (acc[nb][1] - mu0) * rs0 * ls.y + lb.y);
        *(float2*)&out[(size_t)(i0 + r1) * DD + d] =
            make_float2((acc[nb][2] - mu1) * rs1 * ls.x + lb.x,
                        (acc[nb][3] - mu1) * rs1 * ls.y + lb.y);
    }
}

// ================= launch =================
extern "C" void kernel_launch(void* const* d_in, const int* in_sizes, int n_in,
                              void* d_out, int out_size) {
    const float* X     = (const float*)d_in[0];
    const float* M     = (const float*)d_in[1];
    const float* W_in  = (const float*)d_in[2];
    const float* b_in  = (const float*)d_in[3];
    const float* W_out = (const float*)d_in[4];
    const float* b_out = (const float*)d_in[5];
    const float* ln_s  = (const float*)d_in[6];
    const float* ln_b  = (const float*)d_in[7];
    float* out = (float*)d_out;

    cudaFuncSetAttribute(pre_kernel, cudaFuncAttributeMaxDynamicSharedMemorySize, PRE_SMEM);

    pre_kernel<<<384, 256, PRE_SMEM>>>(M, X, W_in, b_in);  // T-GEMM || colsum (+wsum=0)
    mma_kernel<<<296, 256>>>(M);                           // inv computed in-kernel
    epi_kernel<<<256, 256>>>(X, W_out, b_out, ln_s, ln_b, out);
}